// round 1
// baseline (speedup 1.0000x reference)
#include <cuda_runtime.h>
#include <cstdint>

// Problem constants
#define BB 16
#define NL 64
#define NP 512
#define HH 128
#define GG 10
#define GP 32                       // padded combined-G (10+10+10 -> 32)
#define M_TOTAL (BB*NL*NP)          // 524288 rows
#define ATOMS 24

// Output layout in d_out (float32, concatenated in reference return order)
#define PI_OFF   0LL
#define SG_OFF   5242880LL          // M_TOTAL*10
#define MU_OFF   10485760LL
#define D_OFF    15728640LL
#define MK_OFF   16252928LL

// Packed weights/biases scratch (no cudaMalloc allowed)
__device__ float g_Wc[HH * GP];
__device__ float g_bc[GP];

// ---------------------------------------------------------------------------
// Pack W_pi|W_sigma|W_mu -> [128][32] (g 0..9 pi, 10..19 sigma, 20..29 mu)
// ---------------------------------------------------------------------------
__global__ void pack_weights(const float* __restrict__ Wpi,
                             const float* __restrict__ Wsig,
                             const float* __restrict__ Wmu,
                             const float* __restrict__ bpi,
                             const float* __restrict__ bsig,
                             const float* __restrict__ bmu) {
    int k = blockIdx.x;      // 0..127
    int g = threadIdx.x;     // 0..31
    float v = 0.0f;
    if (g < 10)       v = Wpi[k * GG + g];
    else if (g < 20)  v = Wsig[k * GG + (g - 10)];
    else if (g < 30)  v = Wmu[k * GG + (g - 20)];
    g_Wc[k * GP + g] = v;
    if (k == 0) {
        float bv = 0.0f;
        if (g < 10)       bv = bpi[g];
        else if (g < 20)  bv = bsig[g - 10];
        else if (g < 30)  bv = bmu[g - 20];
        g_bc[g] = bv;
    }
}

// ---------------------------------------------------------------------------
// Min-distance kernel: one thread per residue j, 24 atoms in registers,
// loops 32 ligand positions (blockIdx.z selects i-half).
// ---------------------------------------------------------------------------
__global__ __launch_bounds__(128)
void dist_kernel(const float* __restrict__ pos_l,
                 const float* __restrict__ pos_p,
                 const int*   __restrict__ mask,
                 float* __restrict__ dist_out,
                 float* __restrict__ mask_out) {
    int b  = blockIdx.x;            // 16
    int jt = blockIdx.y;            // 4 tiles of 128 j
    int ih = blockIdx.z;            // 2 halves of i
    int t  = threadIdx.x;           // 128
    int j  = jt * 128 + t;
    int i0 = ih * 32;

    __shared__ float4 xl[32];       // (x,y,z,|x|^2) for 32 ligand points
    if (t < 32) {
        int i = i0 + t;
        const float* p = pos_l + ((long long)(b * NL + i)) * 3;
        float x = p[0], y = p[1], z = p[2];
        xl[t] = make_float4(x, y, z, x * x + y * y + z * z);
    }
    __syncthreads();

    // Load this residue's 24 atoms into registers
    float4 A[ATOMS];
    const float* pb = pos_p + (((long long)(b * NP + j)) * ATOMS) * 3;
#pragma unroll
    for (int a = 0; a < ATOMS; a++) {
        float x = pb[a * 3 + 0];
        float y = pb[a * 3 + 1];
        float z = pb[a * 3 + 2];
        A[a] = make_float4(x, y, z, x * x + y * y + z * z);
    }

    for (int ii = 0; ii < 32; ii++) {
        int i = i0 + ii;
        float4 q = xl[ii];
        float m2 = 1e30f;
#pragma unroll
        for (int a = 0; a < ATOMS; a++) {
            float dot = A[a].x * q.x + A[a].y * q.y + A[a].z * q.z;
            float d2 = (q.w + A[a].w) - 2.0f * dot;   // same formula as reference
            d2 = (d2 < 0.0f) ? 1e30f : d2;            // sqrt(neg)=NaN -> 10000
            m2 = fminf(m2, d2);
        }
        float d = (m2 > 9e29f) ? 10000.0f : sqrtf(m2);
        long long idx = ((long long)(b * NL + i)) * NP + j;
        bool mk = (mask[idx] != 0);
        dist_out[idx] = mk ? d : 0.0f;
        mask_out[idx] = mk ? 1.0f : 0.0f;
    }
}

// ---------------------------------------------------------------------------
// GEMM [M,128]x[128,30] + epilogue (softmax / leaky variants), packed f32x2.
// 128 rows per block, one thread per row. X tile + W staged in dynamic smem.
// ---------------------------------------------------------------------------
#define RPB 128
#define SPAD 132    // padded row stride in floats (16B-aligned, low LDS conflicts)
#define GEMM_SMEM ((RPB*SPAD + HH*GP + GP) * 4)

__global__ __launch_bounds__(128)
void gemm_epi(const float* __restrict__ X, float* __restrict__ out) {
    extern __shared__ float smem[];
    float* xs = smem;                       // RPB*SPAD
    float* ws = smem + RPB * SPAD;          // HH*GP
    float* bs = ws + HH * GP;               // GP

    int tid = threadIdx.x;
    long long row0 = (long long)blockIdx.x * RPB;

    // Stage packed weights (broadcast later)
    for (int idx = tid; idx < HH * GP / 4; idx += RPB)
        ((float4*)ws)[idx] = ((const float4*)g_Wc)[idx];
    if (tid < GP) bs[tid] = g_bc[tid];

    // Stage Interact tile: 128 rows x 128 K, fully coalesced float4 loads
    const float4* Xg = (const float4*)(X + row0 * HH);
    for (int idx = tid; idx < RPB * HH / 4; idx += RPB) {
        int r = idx >> 5;
        int c = idx & 31;
        *(float4*)&xs[r * SPAD + c * 4] = Xg[idx];
    }
    __syncthreads();

    // Accumulators: 16 packed f32x2 pairs (30 real outputs + 2 pad)
    unsigned long long acc[16];
#pragma unroll
    for (int g = 0; g < 16; g++) {
        float b0 = bs[2 * g], b1 = bs[2 * g + 1];
        asm("mov.b64 %0, {%1, %2};" : "=l"(acc[g]) : "f"(b0), "f"(b1));
    }

    const float* xr = xs + tid * SPAD;
#pragma unroll 4
    for (int kk = 0; kk < 32; kk++) {
        float4 x4 = *(const float4*)&xr[kk * 4];
#pragma unroll
        for (int e = 0; e < 4; e++) {
            float xk = (e == 0) ? x4.x : (e == 1) ? x4.y : (e == 2) ? x4.z : x4.w;
            unsigned long long xx;
            asm("mov.b64 %0, {%1, %1};" : "=l"(xx) : "f"(xk));
            const ulonglong2* wrow = (const ulonglong2*)&ws[(kk * 4 + e) * GP];
#pragma unroll
            for (int g4 = 0; g4 < 8; g4++) {
                ulonglong2 w2 = wrow[g4];    // LDS.128 broadcast: 2 f32 pairs
                asm("fma.rn.f32x2 %0, %1, %2, %0;" : "+l"(acc[2 * g4])     : "l"(xx), "l"(w2.x));
                asm("fma.rn.f32x2 %0, %1, %2, %0;" : "+l"(acc[2 * g4 + 1]) : "l"(xx), "l"(w2.y));
            }
        }
    }

    // Unpack
    float v[32];
#pragma unroll
    for (int g = 0; g < 16; g++)
        asm("mov.b64 {%0, %1}, %2;" : "=f"(v[2 * g]), "=f"(v[2 * g + 1]) : "l"(acc[g]));

    long long m = row0 + tid;

    // pi = softmax(v[0..9])
    float mx = v[0];
#pragma unroll
    for (int g = 1; g < 10; g++) mx = fmaxf(mx, v[g]);
    float e[10], s = 0.0f;
#pragma unroll
    for (int g = 0; g < 10; g++) { e[g] = __expf(v[g] - mx); s += e[g]; }
    float inv = __fdividef(1.0f, s);
    float* po = out + PI_OFF + m * 10;
#pragma unroll
    for (int g = 0; g < 10; g++) po[g] = e[g] * inv;

    // sigma = clamp(leaky(v)+1.1, 1e-6, inf); mu = leaky(v)+1.0
    float* so = out + SG_OFF + m * 10;
    float* mo = out + MU_OFF + m * 10;
#pragma unroll
    for (int g = 0; g < 10; g++) {
        float xsg = v[10 + g];
        float lsg = (xsg > 0.0f) ? xsg : 0.01f * xsg;
        so[g] = fmaxf(lsg + 1.1f, 1e-6f);
        float xmu = v[20 + g];
        float lmu = (xmu > 0.0f) ? xmu : 0.01f * xmu;
        mo[g] = lmu + 1.0f;
    }
}

// ---------------------------------------------------------------------------
extern "C" void kernel_launch(void* const* d_in, const int* in_sizes, int n_in,
                              void* d_out, int out_size) {
    const float* pos_l    = (const float*)d_in[0];
    const float* pos_p    = (const float*)d_in[1];
    const float* Interact = (const float*)d_in[2];
    const int*   mask     = (const int*)d_in[3];
    const float* W_pi     = (const float*)d_in[4];
    const float* b_pi     = (const float*)d_in[5];
    const float* W_sigma  = (const float*)d_in[6];
    const float* b_sigma  = (const float*)d_in[7];
    const float* W_mu     = (const float*)d_in[8];
    const float* b_mu     = (const float*)d_in[9];
    float* out = (float*)d_out;

    pack_weights<<<HH, GP>>>(W_pi, W_sigma, W_mu, b_pi, b_sigma, b_mu);

    dist_kernel<<<dim3(BB, 4, 2), 128>>>(pos_l, pos_p, mask,
                                         out + D_OFF, out + MK_OFF);

    cudaFuncSetAttribute(gemm_epi, cudaFuncAttributeMaxDynamicSharedMemorySize,
                         GEMM_SMEM);
    gemm_epi<<<M_TOTAL / RPB, RPB, GEMM_SMEM>>>(Interact, out);
}

// round 2
// speedup vs baseline: 1.8968x; 1.8968x over previous
#include <cuda_runtime.h>
#include <cuda_bf16.h>
#include <cstdint>

#define BB 16
#define NL 64
#define NP 512
#define HH 128

// Output layout in d_out (float32, reference return order)
#define PI_OFF   0LL
#define SG_OFF   5242880LL          // M*10
#define MU_OFF   10485760LL
#define D_OFF    15728640LL
#define MK_OFF   16252928LL

// smem layout (float offsets)
#define XBUF_F   18432              // 512 rows * 36 (TK=32 + 4 pad)
#define WH_F     (2*XBUF_F)         // 36864: packed bf16x2 W-hi [64 kpair][33]
#define WL_F     (WH_F + 64*33)     // 38976: W-lo
#define BS_F     (WL_F + 64*33)     // 41088: bias[32]
#define OUT_F    (BS_F + 32)        // 41120: out staging [3][512][10]
#define SMEM_F   (OUT_F + 3*512*10) // 56480 floats
#define SMEM_BYTES (SMEM_F*4)       // 225920 B

// m16n8k16 bf16 MMA, fp32 accumulate
#define MMA(D, A, B0, B1) \
  asm volatile("mma.sync.aligned.m16n8k16.row.col.f32.bf16.bf16.f32 " \
      "{%0,%1,%2,%3}, {%4,%5,%6,%7}, {%8,%9}, {%0,%1,%2,%3};" \
      : "+f"((D)[0]), "+f"((D)[1]), "+f"((D)[2]), "+f"((D)[3]) \
      : "r"((A)[0]), "r"((A)[1]), "r"((A)[2]), "r"((A)[3]), "r"(B0), "r"(B1))

// split float2 -> bf16x2 hi + bf16x2 residual (lo)
#define SPLIT2(f, AH, AL) do { \
    __nv_bfloat16 _h0 = __float2bfloat16((f).x), _h1 = __float2bfloat16((f).y); \
    __nv_bfloat162 _hh; _hh.x = _h0; _hh.y = _h1; \
    (AH) = *(unsigned*)&_hh; \
    __nv_bfloat162 _ll = __floats2bfloat162_rn((f).x - __bfloat162float(_h0), \
                                               (f).y - __bfloat162float(_h1)); \
    (AL) = *(unsigned*)&_ll; } while (0)

__device__ __forceinline__ void cp_async16(void* dst_smem, const void* src) {
    unsigned d = (unsigned)__cvta_generic_to_shared(dst_smem);
    asm volatile("cp.async.cg.shared.global [%0], [%1], 16;\n" :: "r"(d), "l"(src));
}

__global__ __launch_bounds__(256, 1)
void fused_kernel(const float* __restrict__ pos_l, const float* __restrict__ pos_p,
                  const float* __restrict__ X, const int* __restrict__ mask,
                  const float* __restrict__ Wpi, const float* __restrict__ bpi,
                  const float* __restrict__ Wsig, const float* __restrict__ bsig,
                  const float* __restrict__ Wmu, const float* __restrict__ bmu,
                  float* __restrict__ out)
{
    extern __shared__ float sm[];
    unsigned* whU = (unsigned*)(sm + WH_F);
    unsigned* wlU = (unsigned*)(sm + WL_F);
    float* bs = sm + BS_F;
    float* ob = sm + OUT_F;

    const int tid  = threadIdx.x;
    const int lane = tid & 31, w = tid >> 5;
    const int qd   = lane & 3, g4 = lane >> 2;   // g4: A/D row-in-tile AND B col
    const int blk  = blockIdx.x;                 // = b*64 + i
    const int b    = blk >> 6;
    const long long m0 = (long long)blk * 512;

    // ---- prefetch GEMM chunk 0 into buf0 (overlaps with dist phase) ----
    {
        const float4* Xg = (const float4*)X;
        #pragma unroll
        for (int it = 0; it < 16; it++) {
            int idx = it*256 + tid;
            int row = idx >> 3, c4 = idx & 7;
            cp_async16(sm + row*36 + c4*4, Xg + (m0 + row)*32 + c4);
        }
        asm volatile("cp.async.commit_group;\n");
    }

    // ---- phase 0: pack W (bf16 hi/lo, k-pairs) + bias into smem ----
    for (int idx = tid; idx < 64*32; idx += 256) {
        int kp = idx >> 5, g = idx & 31;
        int k0 = kp*2, k1 = k0 + 1;
        float w0 = 0.f, w1 = 0.f;
        if (g < 10)      { w0 = Wpi [k0*10 + g];      w1 = Wpi [k1*10 + g]; }
        else if (g < 20) { w0 = Wsig[k0*10 + g - 10]; w1 = Wsig[k1*10 + g - 10]; }
        else if (g < 30) { w0 = Wmu [k0*10 + g - 20]; w1 = Wmu [k1*10 + g - 20]; }
        __nv_bfloat16 h0 = __float2bfloat16(w0), h1 = __float2bfloat16(w1);
        __nv_bfloat162 hh; hh.x = h0; hh.y = h1;
        __nv_bfloat162 ll = __floats2bfloat162_rn(w0 - __bfloat162float(h0),
                                                  w1 - __bfloat162float(h1));
        whU[kp*33 + g] = *(unsigned*)&hh;
        wlU[kp*33 + g] = *(unsigned*)&ll;
    }
    if (tid < 32) {
        float bv = 0.f;
        if (tid < 10) bv = bpi[tid];
        else if (tid < 20) bv = bsig[tid - 10];
        else if (tid < 30) bv = bmu[tid - 20];
        bs[tid] = bv;
    }

    // ---- phase 1: min-distance + mask (uses buf1 region for atoms) ----
    {
        const int i = blk & 63;
        const float* p = pos_l + ((long long)(b*NL + i))*3;
        float qx = p[0], qy = p[1], qz = p[2];
        float qw = qx*qx + qy*qy + qz*qz;
        float* ab = sm + XBUF_F;
        const float4* pp = (const float4*)(pos_p + (long long)b * NP * 72);
        for (int half = 0; half < 2; half++) {
            #pragma unroll
            for (int it = 0; it < 18; it++) {
                int idx = it*256 + tid;
                ((float4*)ab)[idx] = pp[half*4608 + idx];
            }
            __syncthreads();
            const float* A = ab + tid*72;
            float m2 = 1e30f;
            #pragma unroll
            for (int a = 0; a < 24; a++) {
                float ax = A[a*3], ay = A[a*3+1], az = A[a*3+2];
                float aw = ax*ax + ay*ay + az*az;
                float d2 = (qw + aw) - 2.f*(ax*qx + ay*qy + az*qz);
                d2 = (d2 < 0.f) ? 1e30f : d2;   // sqrt(neg)=NaN -> 10000 path
                m2 = fminf(m2, d2);
            }
            float d = (m2 > 9e29f) ? 10000.f : sqrtf(m2);
            long long m = m0 + half*256 + tid;
            bool mk = (mask[m] != 0);
            out[D_OFF + m]  = mk ? d : 0.f;
            out[MK_OFF + m] = mk ? 1.f : 0.f;
            __syncthreads();
        }
    }

    // ---- phase 2: GEMM [512,128]x[128,32] via bf16 MMA, 3-term split ----
    float acc[4][4][4];
    #pragma unroll
    for (int mt = 0; mt < 4; mt++)
        #pragma unroll
        for (int n = 0; n < 4; n++) {
            float c0 = bs[8*n + 2*qd], c1 = bs[8*n + 2*qd + 1];
            acc[mt][n][0] = c0; acc[mt][n][1] = c1;
            acc[mt][n][2] = c0; acc[mt][n][3] = c1;
        }

    const float4* Xg = (const float4*)X;
    for (int c = 0; c < 4; c++) {
        if (c < 3) {
            float* bufn = sm + ((c+1) & 1) * XBUF_F;
            #pragma unroll
            for (int it = 0; it < 16; it++) {
                int idx = it*256 + tid;
                int row = idx >> 3, c4 = idx & 7;
                cp_async16(bufn + row*36 + c4*4, Xg + (m0 + row)*32 + (c+1)*8 + c4);
            }
            asm volatile("cp.async.commit_group;\n");
            asm volatile("cp.async.wait_group 1;\n");
        } else {
            asm volatile("cp.async.wait_group 0;\n");
        }
        __syncthreads();
        const float* buf = sm + (c & 1) * XBUF_F;
        #pragma unroll
        for (int s = 0; s < 2; s++) {
            int ks = 2*c + s;                      // global k16-step 0..7
            unsigned bh0[4], bh1[4], bl0[4], bl1[4];
            #pragma unroll
            for (int n = 0; n < 4; n++) {
                int col = 8*n + g4;
                bh0[n] = whU[(8*ks + qd)*33 + col];
                bh1[n] = whU[(8*ks + qd + 4)*33 + col];
                bl0[n] = wlU[(8*ks + qd)*33 + col];
                bl1[n] = wlU[(8*ks + qd + 4)*33 + col];
            }
            #pragma unroll
            for (int mt = 0; mt < 4; mt++) {
                const float* base = buf + (64*w + 16*mt + g4)*36 + s*16 + 2*qd;
                float2 x00 = *(const float2*)(base);
                float2 x01 = *(const float2*)(base + 8);
                float2 x10 = *(const float2*)(base + 288);
                float2 x11 = *(const float2*)(base + 296);
                unsigned ah[4], al[4];
                SPLIT2(x00, ah[0], al[0]);
                SPLIT2(x10, ah[1], al[1]);
                SPLIT2(x01, ah[2], al[2]);
                SPLIT2(x11, ah[3], al[3]);
                #pragma unroll
                for (int n = 0; n < 4; n++) {
                    MMA(acc[mt][n], ah, bh0[n], bh1[n]);   // hi * Whi
                    MMA(acc[mt][n], al, bh0[n], bh1[n]);   // lo * Whi
                    MMA(acc[mt][n], ah, bl0[n], bl1[n]);   // hi * Wlo
                }
            }
        }
        __syncthreads();
    }

    // ---- epilogue: softmax / leaky in fragment layout, stage to smem ----
    #pragma unroll
    for (int mt = 0; mt < 4; mt++) {
        int rbase = 64*w + 16*mt + g4;
        #pragma unroll
        for (int h = 0; h < 2; h++) {
            int r = rbase + 8*h;
            float v0[4], v1[4];
            #pragma unroll
            for (int n = 0; n < 4; n++) {
                v0[n] = acc[mt][n][2*h];
                v1[n] = acc[mt][n][2*h + 1];
            }
            // pi = softmax over cols 0..9 (quad-local reduce)
            float mx = fmaxf(v0[0], v1[0]);
            if (qd == 0) mx = fmaxf(mx, fmaxf(v0[1], v1[1]));
            mx = fmaxf(mx, __shfl_xor_sync(0xffffffffu, mx, 1));
            mx = fmaxf(mx, __shfl_xor_sync(0xffffffffu, mx, 2));
            float e0 = __expf(v0[0] - mx), e1 = __expf(v1[0] - mx);
            float e8 = 0.f, e9 = 0.f;
            float ssum = e0 + e1;
            if (qd == 0) { e8 = __expf(v0[1] - mx); e9 = __expf(v1[1] - mx); ssum += e8 + e9; }
            ssum += __shfl_xor_sync(0xffffffffu, ssum, 1);
            ssum += __shfl_xor_sync(0xffffffffu, ssum, 2);
            float inv = __fdividef(1.f, ssum);
            float* prow = ob + r*10;
            *(float2*)(prow + 2*qd) = make_float2(e0*inv, e1*inv);
            if (qd == 0) *(float2*)(prow + 8) = make_float2(e8*inv, e9*inv);
            // sigma = max(leaky(v)+1.1, 1e-6): cols 10..19
            float* srow = ob + 5120 + r*10;
            if (qd >= 1) {
                float a0 = v0[1], a1 = v1[1];                       // cols 8+2qd
                float l0 = (a0 > 0.f) ? a0 : 0.01f*a0;
                float l1 = (a1 > 0.f) ? a1 : 0.01f*a1;
                *(float2*)(srow + 2*qd - 2) =
                    make_float2(fmaxf(l0 + 1.1f, 1e-6f), fmaxf(l1 + 1.1f, 1e-6f));
            }
            if (qd <= 1) {
                float a0 = v0[2], a1 = v1[2];                       // cols 16+2qd
                float l0 = (a0 > 0.f) ? a0 : 0.01f*a0;
                float l1 = (a1 > 0.f) ? a1 : 0.01f*a1;
                *(float2*)(srow + 6 + 2*qd) =
                    make_float2(fmaxf(l0 + 1.1f, 1e-6f), fmaxf(l1 + 1.1f, 1e-6f));
            }
            // mu = leaky(v)+1.0: cols 20..29
            float* mrow = ob + 10240 + r*10;
            if (qd >= 2) {
                float a0 = v0[2], a1 = v1[2];                       // cols 16+2qd (20..23)
                float l0 = (a0 > 0.f) ? a0 : 0.01f*a0;
                float l1 = (a1 > 0.f) ? a1 : 0.01f*a1;
                *(float2*)(mrow + 2*qd - 4) = make_float2(l0 + 1.f, l1 + 1.f);
            }
            if (qd <= 2) {
                float a0 = v0[3], a1 = v1[3];                       // cols 24+2qd (24..29)
                float l0 = (a0 > 0.f) ? a0 : 0.01f*a0;
                float l1 = (a1 > 0.f) ? a1 : 0.01f*a1;
                *(float2*)(mrow + 4 + 2*qd) = make_float2(l0 + 1.f, l1 + 1.f);
            }
        }
    }
    __syncthreads();

    // ---- coalesced float4 store of the three 20KB regions ----
    const float4* obv = (const float4*)ob;
    #pragma unroll
    for (int it = 0; it < 15; it++) {
        int idx = it*256 + tid;
        int reg = idx / 1280, wi = idx % 1280;
        long long goff = (reg == 0 ? PI_OFF : reg == 1 ? SG_OFF : MU_OFF) + m0*10;
        *((float4*)(out + goff) + wi) = obv[idx];
    }
}

extern "C" void kernel_launch(void* const* d_in, const int* in_sizes, int n_in,
                              void* d_out, int out_size) {
    const float* pos_l    = (const float*)d_in[0];
    const float* pos_p    = (const float*)d_in[1];
    const float* Interact = (const float*)d_in[2];
    const int*   mask     = (const int*)d_in[3];
    const float* W_pi     = (const float*)d_in[4];
    const float* b_pi     = (const float*)d_in[5];
    const float* W_sigma  = (const float*)d_in[6];
    const float* b_sigma  = (const float*)d_in[7];
    const float* W_mu     = (const float*)d_in[8];
    const float* b_mu     = (const float*)d_in[9];
    float* out = (float*)d_out;

    cudaFuncSetAttribute(fused_kernel, cudaFuncAttributeMaxDynamicSharedMemorySize,
                         SMEM_BYTES);
    fused_kernel<<<BB * NL, 256, SMEM_BYTES>>>(pos_l, pos_p, Interact, mask,
                                               W_pi, b_pi, W_sigma, b_sigma,
                                               W_mu, b_mu, out);
}

// round 3
// speedup vs baseline: 2.0866x; 1.1001x over previous
#include <cuda_runtime.h>
#include <cuda_bf16.h>
#include <cstdint>

#define BB 16
#define NL 64
#define NP 512
#define HH 128

// Output layout in d_out (float32, reference return order)
#define PI_OFF   0LL
#define SG_OFF   5242880LL          // M*10
#define MU_OFF   10485760LL
#define D_OFF    15728640LL
#define MK_OFF   16252928LL

// smem layout (u32 offsets). bf16 X buffers; W; bias. Epilogue staging aliases X.
#define HI_U     0                  // hi[512][20] u32
#define LO_U     10240              // lo[512][20]
#define WH_U     20480              // whU[64][33]
#define WL_U     (WH_U + 64*33)     // 22592
#define BS_U     (WL_U + 64*33)     // 24704
#define OB_U     0                  // out staging [3][512][10] f32, aliases HI/LO
#define SMEM_U   (BS_U + 32)        // 24736 u32
#define SMEM_BYTES (SMEM_U*4)       // 98944 B

// m16n8k16 bf16 MMA, fp32 accumulate
#define MMA(D, A, B0, B1) \
  asm volatile("mma.sync.aligned.m16n8k16.row.col.f32.bf16.bf16.f32 " \
      "{%0,%1,%2,%3}, {%4,%5,%6,%7}, {%8,%9}, {%0,%1,%2,%3};" \
      : "+f"((D)[0]), "+f"((D)[1]), "+f"((D)[2]), "+f"((D)[3]) \
      : "r"((A)[0]), "r"((A)[1]), "r"((A)[2]), "r"((A)[3]), "r"(B0), "r"(B1))

// float4 -> 2x bf16x2 hi + 2x bf16x2 residual
__device__ __forceinline__ void split4(float4 v, uint2& hv, uint2& lv) {
    __nv_bfloat162 h0 = __floats2bfloat162_rn(v.x, v.y);
    __nv_bfloat162 h1 = __floats2bfloat162_rn(v.z, v.w);
    float2 f0 = __bfloat1622float2(h0);
    float2 f1 = __bfloat1622float2(h1);
    __nv_bfloat162 l0 = __floats2bfloat162_rn(v.x - f0.x, v.y - f0.y);
    __nv_bfloat162 l1 = __floats2bfloat162_rn(v.z - f1.x, v.w - f1.y);
    hv = make_uint2(*(unsigned*)&h0, *(unsigned*)&h1);
    lv = make_uint2(*(unsigned*)&l0, *(unsigned*)&l1);
}

__global__ __launch_bounds__(512, 1)
void fused_kernel(const float* __restrict__ pos_l, const float* __restrict__ pos_p,
                  const float* __restrict__ X, const int* __restrict__ mask,
                  const float* __restrict__ Wpi, const float* __restrict__ bpi,
                  const float* __restrict__ Wsig, const float* __restrict__ bsig,
                  const float* __restrict__ Wmu, const float* __restrict__ bmu,
                  float* __restrict__ out)
{
    extern __shared__ unsigned smU[];
    unsigned* hiU = smU + HI_U;
    unsigned* loU = smU + LO_U;
    unsigned* whU = smU + WH_U;
    unsigned* wlU = smU + WL_U;
    float*    bs  = (float*)(smU + BS_U);
    float*    ob  = (float*)(smU + OB_U);

    const int tid  = threadIdx.x;
    const int lane = tid & 31, w = tid >> 5;
    const int qd   = lane & 3, g4 = lane >> 2;
    const int blk  = blockIdx.x;                 // = b*64 + i
    const int b    = blk >> 6;
    const long long m0 = (long long)blk * 512;
    const float4* Xg = (const float4*)X;

    // ---- prefetch GEMM chunk 0 straight into registers ----
    float4 xr[8];
    #pragma unroll
    for (int it = 0; it < 8; it++) {
        int idx = it*512 + tid;
        xr[it] = Xg[(m0 + (idx >> 3))*32 + (idx & 7)];
    }

    // ---- pack W (bf16 hi/lo, k-pairs) + bias into smem ----
    for (int idx = tid; idx < 64*32; idx += 512) {
        int kp = idx >> 5, g = idx & 31;
        int k0 = kp*2, k1 = k0 + 1;
        float w0 = 0.f, w1 = 0.f;
        if (g < 10)      { w0 = Wpi [k0*10 + g];      w1 = Wpi [k1*10 + g]; }
        else if (g < 20) { w0 = Wsig[k0*10 + g - 10]; w1 = Wsig[k1*10 + g - 10]; }
        else if (g < 30) { w0 = Wmu [k0*10 + g - 20]; w1 = Wmu [k1*10 + g - 20]; }
        __nv_bfloat162 hh = __floats2bfloat162_rn(w0, w1);
        float2 hf = __bfloat1622float2(hh);
        __nv_bfloat162 ll = __floats2bfloat162_rn(w0 - hf.x, w1 - hf.y);
        whU[kp*33 + g] = *(unsigned*)&hh;
        wlU[kp*33 + g] = *(unsigned*)&ll;
    }
    if (tid < 32) {
        float bv = 0.f;
        if (tid < 10) bv = bpi[tid];
        else if (tid < 20) bv = bsig[tid - 10];
        else if (tid < 30) bv = bmu[tid - 20];
        bs[tid] = bv;
    }

    // ---- min-distance + mask: one thread per j, atoms direct from L2 ----
    {
        const int i = blk & 63;
        const float* p = pos_l + ((long long)(b*NL + i))*3;
        float qx = p[0], qy = p[1], qz = p[2];
        float qw = qx*qx + qy*qy + qz*qz;
        const float4* A4 = (const float4*)(pos_p + ((long long)b*NP + tid)*72);
        float4 av[18];
        #pragma unroll
        for (int u = 0; u < 18; u++) av[u] = A4[u];
        const float* A = (const float*)av;
        float m2 = 1e30f;
        #pragma unroll
        for (int a = 0; a < 24; a++) {
            float ax = A[a*3], ay = A[a*3+1], az = A[a*3+2];
            float aw = ax*ax + ay*ay + az*az;
            float d2 = (qw + aw) - 2.f*(ax*qx + ay*qy + az*qz);
            d2 = (d2 < 0.f) ? 1e30f : d2;      // sqrt(neg)=NaN -> 10000 path
            m2 = fminf(m2, d2);
        }
        float d = (m2 > 9e29f) ? 10000.f : sqrtf(m2);
        long long m = m0 + tid;
        bool mk = (mask[m] != 0);
        out[D_OFF + m]  = mk ? d : 0.f;
        out[MK_OFF + m] = mk ? 1.f : 0.f;
    }
    __syncthreads();   // bias/W visible

    // ---- GEMM [512,128]x[128,32]: bf16 MMA, 3-term compensated ----
    float acc[2][4][4];
    #pragma unroll
    for (int mt = 0; mt < 2; mt++)
        #pragma unroll
        for (int n = 0; n < 4; n++) {
            float c0 = bs[8*n + 2*qd], c1 = bs[8*n + 2*qd + 1];
            acc[mt][n][0] = c0; acc[mt][n][1] = c1;
            acc[mt][n][2] = c0; acc[mt][n][3] = c1;
        }

    for (int c = 0; c < 4; c++) {
        // convert held chunk to bf16 hi/lo smem
        #pragma unroll
        for (int it = 0; it < 8; it++) {
            int idx = it*512 + tid;
            int r = idx >> 3, j = idx & 7;
            uint2 hv, lv;
            split4(xr[it], hv, lv);
            *(uint2*)&hiU[r*20 + 2*j] = hv;
            *(uint2*)&loU[r*20 + 2*j] = lv;
        }
        // prefetch next chunk into registers (latency hidden by MMA loop)
        if (c < 3) {
            #pragma unroll
            for (int it = 0; it < 8; it++) {
                int idx = it*512 + tid;
                xr[it] = Xg[(m0 + (idx >> 3))*32 + (c+1)*8 + (idx & 7)];
            }
        }
        __syncthreads();
        #pragma unroll
        for (int s = 0; s < 2; s++) {
            int ks = 2*c + s;
            unsigned bh0[4], bh1[4], bl0[4], bl1[4];
            #pragma unroll
            for (int n = 0; n < 4; n++) {
                int col = 8*n + g4;
                bh0[n] = whU[(8*ks + qd)*33 + col];
                bh1[n] = whU[(8*ks + qd + 4)*33 + col];
                bl0[n] = wlU[(8*ks + qd)*33 + col];
                bl1[n] = wlU[(8*ks + qd + 4)*33 + col];
            }
            #pragma unroll
            for (int mt = 0; mt < 2; mt++) {
                int row = 32*w + 16*mt + g4;
                unsigned ah[4], al[4];
                ah[0] = hiU[ row     *20 + 8*s + qd];
                ah[1] = hiU[(row + 8)*20 + 8*s + qd];
                ah[2] = hiU[ row     *20 + 8*s + 4 + qd];
                ah[3] = hiU[(row + 8)*20 + 8*s + 4 + qd];
                al[0] = loU[ row     *20 + 8*s + qd];
                al[1] = loU[(row + 8)*20 + 8*s + qd];
                al[2] = loU[ row     *20 + 8*s + 4 + qd];
                al[3] = loU[(row + 8)*20 + 8*s + 4 + qd];
                #pragma unroll
                for (int n = 0; n < 4; n++) {
                    MMA(acc[mt][n], ah, bh0[n], bh1[n]);   // hi * Whi
                    MMA(acc[mt][n], al, bh0[n], bh1[n]);   // lo * Whi
                    MMA(acc[mt][n], ah, bl0[n], bl1[n]);   // hi * Wlo
                }
            }
        }
        __syncthreads();   // MMA reads done before next convert overwrites
    }

    // ---- epilogue in fragment layout, stage to smem (aliases X bufs) ----
    #pragma unroll
    for (int mt = 0; mt < 2; mt++) {
        int rbase = 32*w + 16*mt + g4;
        #pragma unroll
        for (int h = 0; h < 2; h++) {
            int r = rbase + 8*h;
            float v0[4], v1[4];
            #pragma unroll
            for (int n = 0; n < 4; n++) {
                v0[n] = acc[mt][n][2*h];
                v1[n] = acc[mt][n][2*h + 1];
            }
            // pi = softmax over cols 0..9 (quad reduce)
            float mx = fmaxf(v0[0], v1[0]);
            if (qd == 0) mx = fmaxf(mx, fmaxf(v0[1], v1[1]));
            mx = fmaxf(mx, __shfl_xor_sync(0xffffffffu, mx, 1));
            mx = fmaxf(mx, __shfl_xor_sync(0xffffffffu, mx, 2));
            float e0 = __expf(v0[0] - mx), e1 = __expf(v1[0] - mx);
            float e8 = 0.f, e9 = 0.f;
            float ssum = e0 + e1;
            if (qd == 0) { e8 = __expf(v0[1] - mx); e9 = __expf(v1[1] - mx); ssum += e8 + e9; }
            ssum += __shfl_xor_sync(0xffffffffu, ssum, 1);
            ssum += __shfl_xor_sync(0xffffffffu, ssum, 2);
            float inv = __fdividef(1.f, ssum);
            float* prow = ob + r*10;
            *(float2*)(prow + 2*qd) = make_float2(e0*inv, e1*inv);
            if (qd == 0) *(float2*)(prow + 8) = make_float2(e8*inv, e9*inv);
            // sigma cols 10..19
            float* srow = ob + 5120 + r*10;
            if (qd >= 1) {
                float a0 = v0[1], a1 = v1[1];
                float l0 = (a0 > 0.f) ? a0 : 0.01f*a0;
                float l1 = (a1 > 0.f) ? a1 : 0.01f*a1;
                *(float2*)(srow + 2*qd - 2) =
                    make_float2(fmaxf(l0 + 1.1f, 1e-6f), fmaxf(l1 + 1.1f, 1e-6f));
            }
            if (qd <= 1) {
                float a0 = v0[2], a1 = v1[2];
                float l0 = (a0 > 0.f) ? a0 : 0.01f*a0;
                float l1 = (a1 > 0.f) ? a1 : 0.01f*a1;
                *(float2*)(srow + 6 + 2*qd) =
                    make_float2(fmaxf(l0 + 1.1f, 1e-6f), fmaxf(l1 + 1.1f, 1e-6f));
            }
            // mu cols 20..29
            float* mrow = ob + 10240 + r*10;
            if (qd >= 2) {
                float a0 = v0[2], a1 = v1[2];
                float l0 = (a0 > 0.f) ? a0 : 0.01f*a0;
                float l1 = (a1 > 0.f) ? a1 : 0.01f*a1;
                *(float2*)(mrow + 2*qd - 4) = make_float2(l0 + 1.f, l1 + 1.f);
            }
            if (qd <= 2) {
                float a0 = v0[3], a1 = v1[3];
                float l0 = (a0 > 0.f) ? a0 : 0.01f*a0;
                float l1 = (a1 > 0.f) ? a1 : 0.01f*a1;
                *(float2*)(mrow + 4 + 2*qd) = make_float2(l0 + 1.f, l1 + 1.f);
            }
        }
    }
    __syncthreads();

    // ---- coalesced float4 store of pi/sigma/mu ----
    const float4* obv = (const float4*)ob;
    #pragma unroll
    for (int it = 0; it < 8; it++) {
        int idx = it*512 + tid;
        if (idx < 3840) {
            int reg = idx / 1280, wi = idx % 1280;
            long long goff = (reg == 0 ? PI_OFF : reg == 1 ? SG_OFF : MU_OFF) + m0*10;
            *((float4*)(out + goff) + wi) = obv[idx];
        }
    }
}

extern "C" void kernel_launch(void* const* d_in, const int* in_sizes, int n_in,
                              void* d_out, int out_size) {
    const float* pos_l    = (const float*)d_in[0];
    const float* pos_p    = (const float*)d_in[1];
    const float* Interact = (const float*)d_in[2];
    const int*   mask     = (const int*)d_in[3];
    const float* W_pi     = (const float*)d_in[4];
    const float* b_pi     = (const float*)d_in[5];
    const float* W_sigma  = (const float*)d_in[6];
    const float* b_sigma  = (const float*)d_in[7];
    const float* W_mu     = (const float*)d_in[8];
    const float* b_mu     = (const float*)d_in[9];
    float* out = (float*)d_out;

    cudaFuncSetAttribute(fused_kernel, cudaFuncAttributeMaxDynamicSharedMemorySize,
                         SMEM_BYTES);
    fused_kernel<<<BB * NL, 512, SMEM_BYTES>>>(pos_l, pos_p, Interact, mask,
                                               W_pi, b_pi, W_sigma, b_sigma,
                                               W_mu, b_mu, out);
}

// round 4
// speedup vs baseline: 2.7796x; 1.3321x over previous
#include <cuda_runtime.h>
#include <cuda_bf16.h>
#include <cstdint>

#define BB 16
#define NL 64
#define NP 512

// Output layout in d_out (float32, reference return order)
#define PI_OFF   0LL
#define SG_OFF   5242880LL          // M*10
#define MU_OFF   10485760LL
#define D_OFF    15728640LL
#define MK_OFF   16252928LL

// smem (u32 offsets): wfrag[8 ks][16 which][32 lane], bias[32], out-staging
#define WF_U     0
#define BS_U     4096
#define OB_U     4128               // ob[3][256][10] f32 = 7680
#define SMEM_U   (OB_U + 7680)
#define SMEM_BYTES (SMEM_U*4)       // 47232 B

// m16n8k16 bf16 MMA, fp32 accumulate
#define MMA(D, A, B0, B1) \
  asm volatile("mma.sync.aligned.m16n8k16.row.col.f32.bf16.bf16.f32 " \
      "{%0,%1,%2,%3}, {%4,%5,%6,%7}, {%8,%9}, {%0,%1,%2,%3};" \
      : "+f"((D)[0]), "+f"((D)[1]), "+f"((D)[2]), "+f"((D)[3]) \
      : "r"((A)[0]), "r"((A)[1]), "r"((A)[2]), "r"((A)[3]), "r"(B0), "r"(B1))

// float4 -> 2x bf16x2 hi + 2x bf16x2 residual
__device__ __forceinline__ void split4(float4 v, uint2& hv, uint2& lv) {
    __nv_bfloat162 h0 = __floats2bfloat162_rn(v.x, v.y);
    __nv_bfloat162 h1 = __floats2bfloat162_rn(v.z, v.w);
    float2 f0 = __bfloat1622float2(h0);
    float2 f1 = __bfloat1622float2(h1);
    __nv_bfloat162 l0 = __floats2bfloat162_rn(v.x - f0.x, v.y - f0.y);
    __nv_bfloat162 l1 = __floats2bfloat162_rn(v.z - f1.x, v.w - f1.y);
    hv = make_uint2(*(unsigned*)&h0, *(unsigned*)&h1);
    lv = make_uint2(*(unsigned*)&l0, *(unsigned*)&l1);
}

__global__ __launch_bounds__(256, 2)
void fused_kernel(const float* __restrict__ pos_l, const float* __restrict__ pos_p,
                  const float* __restrict__ X, const int* __restrict__ mask,
                  const float* __restrict__ Wpi, const float* __restrict__ bpi,
                  const float* __restrict__ Wsig, const float* __restrict__ bsig,
                  const float* __restrict__ Wmu, const float* __restrict__ bmu,
                  float* __restrict__ out)
{
    extern __shared__ unsigned smU[];
    unsigned* wf = smU + WF_U;
    float*    bs = (float*)(smU + BS_U);
    float*    ob = (float*)(smU + OB_U);

    const int tid  = threadIdx.x;
    const int lane = tid & 31, w = tid >> 5;
    const int qd   = lane & 3, g4 = lane >> 2;
    const int blk  = blockIdx.x;                  // 2048 blocks: 256 rows each
    const int b    = blk >> 7;
    const int i    = (blk >> 1) & 63;
    const long long m0 = (long long)blk * 256;

    // ---- pack W fragments in exact warp-lane order (k-permuted) ----
    // wf[ks*512 + which*32 + lane]; which = type*4+n; type: 0 bh0,1 bh1,2 bl0,3 bl1
    // bh0/bl0 hold physical k-pair 8ks+2qd ; bh1/bl1 hold 8ks+2qd+1 (perm sigma)
    #pragma unroll
    for (int it = 0; it < 16; it++) {
        int idx  = it*256 + tid;
        int ksw  = idx >> 9;
        int which = (idx >> 5) & 15;
        int ln   = idx & 31;
        int n    = which & 3, type = which >> 2;
        int qd_  = ln & 3,  g4_ = ln >> 2;
        int col  = 8*n + g4_;
        int kp   = 8*ksw + 2*qd_ + (type & 1);    // k-pair: rows 2kp, 2kp+1
        float w0 = 0.f, w1 = 0.f;
        if (col < 10)      { w0 = Wpi [kp*20 + col];      w1 = Wpi [kp*20 + 10 + col]; }
        else if (col < 20) { w0 = Wsig[kp*20 + col - 10]; w1 = Wsig[kp*20 + col]; }
        else if (col < 30) { w0 = Wmu [kp*20 + col - 20]; w1 = Wmu [kp*20 + col - 10]; }
        __nv_bfloat162 hh = __floats2bfloat162_rn(w0, w1);
        if (type >= 2) {    // residual (lo) fragments
            float2 hf = __bfloat1622float2(hh);
            hh = __floats2bfloat162_rn(w0 - hf.x, w1 - hf.y);
        }
        wf[idx] = *(unsigned*)&hh;
    }
    if (tid < 32) {
        float bv = 0.f;
        if (tid < 10) bv = bpi[tid];
        else if (tid < 20) bv = bsig[tid - 10];
        else if (tid < 30) bv = bmu[tid - 20];
        bs[tid] = bv;
    }

    // ---- min-distance + mask: one thread per j (atoms from L2) ----
    {
        const float* p = pos_l + (long long)(b*NL + i)*3;
        float qx = p[0], qy = p[1], qz = p[2];
        float qw = qx*qx + qy*qy + qz*qz;
        long long m = m0 + tid;
        int jg = (int)(m & 511);
        const float4* A4 = (const float4*)(pos_p + ((long long)b*NP + jg)*72);
        float4 av[18];
        #pragma unroll
        for (int u = 0; u < 18; u++) av[u] = A4[u];
        const float* A = (const float*)av;
        float m2 = 1e30f;
        #pragma unroll
        for (int a = 0; a < 24; a++) {
            float ax = A[a*3], ay = A[a*3+1], az = A[a*3+2];
            float aw = ax*ax + ay*ay + az*az;
            float d2 = (qw + aw) - 2.f*(ax*qx + ay*qy + az*qz);
            d2 = (d2 < 0.f) ? 1e30f : d2;       // sqrt(neg)=NaN -> 10000 path
            m2 = fminf(m2, d2);
        }
        float d = (m2 > 9e29f) ? 10000.f : sqrtf(m2);
        bool mk = (mask[m] != 0);
        out[D_OFF + m]  = mk ? d : 0.f;
        out[MK_OFF + m] = mk ? 1.f : 0.f;
    }

    // ---- GEMM [256,128]x[128,32]: A direct from GMEM (k-permuted LDG.128) ----
    // lane (g4,qd) loads float4 at (row 32w+16mt+8r+g4, float4-col 4s+qd)
    const float4* Xr = (const float4*)X + (m0 + 32*w + g4)*32 + qd;
    float4 buf[2][8];   // [pair parity][s2*4 + mt*2 + r]

    #define LOADP(pp, B) { \
        _Pragma("unroll") \
        for (int u2 = 0; u2 < 8; u2++) { \
            int s2_ = u2 >> 2, mt_ = (u2 >> 1) & 1, r_ = u2 & 1; \
            (B)[u2] = Xr[(16*mt_ + 8*r_)*32 + 4*(2*(pp) + s2_)]; \
        } }

    LOADP(0, buf[0]);
    __syncthreads();    // wf/bs visible

    float acc[2][4][4];
    #pragma unroll
    for (int mt = 0; mt < 2; mt++)
        #pragma unroll
        for (int n = 0; n < 4; n++) {
            float c0 = bs[8*n + 2*qd], c1 = bs[8*n + 2*qd + 1];
            acc[mt][n][0] = c0; acc[mt][n][1] = c1;
            acc[mt][n][2] = c0; acc[mt][n][3] = c1;
        }

    #pragma unroll
    for (int p = 0; p < 4; p++) {
        if (p < 3) LOADP(p + 1, buf[(p + 1) & 1]);
        #pragma unroll
        for (int s2 = 0; s2 < 2; s2++) {
            int ks = 2*p + s2;
            const unsigned* wfs = wf + ks*512 + lane;   // conflict-free LDS
            unsigned bw[16];
            #pragma unroll
            for (int q = 0; q < 16; q++) bw[q] = wfs[q*32];
            #pragma unroll
            for (int mt = 0; mt < 2; mt++) {
                float4 x0 = buf[p & 1][s2*4 + 2*mt];
                float4 x1 = buf[p & 1][s2*4 + 2*mt + 1];
                uint2 h0, l0, h1, l1;
                split4(x0, h0, l0); split4(x1, h1, l1);
                unsigned ah[4] = {h0.x, h1.x, h0.y, h1.y};
                unsigned al[4] = {l0.x, l1.x, l0.y, l1.y};
                #pragma unroll
                for (int n = 0; n < 4; n++) {
                    MMA(acc[mt][n], ah, bw[n],     bw[4 + n]);    // hi*Whi
                    MMA(acc[mt][n], al, bw[n],     bw[4 + n]);    // lo*Whi
                    MMA(acc[mt][n], ah, bw[8 + n], bw[12 + n]);   // hi*Wlo
                }
            }
        }
    }

    // ---- epilogue in fragment layout, stage to smem ----
    #pragma unroll
    for (int mt = 0; mt < 2; mt++) {
        int rbase = 32*w + 16*mt + g4;
        #pragma unroll
        for (int h = 0; h < 2; h++) {
            int r = rbase + 8*h;
            float v0[4], v1[4];
            #pragma unroll
            for (int n = 0; n < 4; n++) {
                v0[n] = acc[mt][n][2*h];
                v1[n] = acc[mt][n][2*h + 1];
            }
            // pi = softmax over cols 0..9 (quad reduce)
            float mx = fmaxf(v0[0], v1[0]);
            if (qd == 0) mx = fmaxf(mx, fmaxf(v0[1], v1[1]));
            mx = fmaxf(mx, __shfl_xor_sync(0xffffffffu, mx, 1));
            mx = fmaxf(mx, __shfl_xor_sync(0xffffffffu, mx, 2));
            float e0 = __expf(v0[0] - mx), e1 = __expf(v1[0] - mx);
            float e8 = 0.f, e9 = 0.f;
            float ssum = e0 + e1;
            if (qd == 0) { e8 = __expf(v0[1] - mx); e9 = __expf(v1[1] - mx); ssum += e8 + e9; }
            ssum += __shfl_xor_sync(0xffffffffu, ssum, 1);
            ssum += __shfl_xor_sync(0xffffffffu, ssum, 2);
            float inv = __fdividef(1.f, ssum);
            float* prow = ob + r*10;
            *(float2*)(prow + 2*qd) = make_float2(e0*inv, e1*inv);
            if (qd == 0) *(float2*)(prow + 8) = make_float2(e8*inv, e9*inv);
            // sigma cols 10..19
            float* srow = ob + 2560 + r*10;
            if (qd >= 1) {
                float a0 = v0[1], a1 = v1[1];
                float l0 = (a0 > 0.f) ? a0 : 0.01f*a0;
                float l1 = (a1 > 0.f) ? a1 : 0.01f*a1;
                *(float2*)(srow + 2*qd - 2) =
                    make_float2(fmaxf(l0 + 1.1f, 1e-6f), fmaxf(l1 + 1.1f, 1e-6f));
            }
            if (qd <= 1) {
                float a0 = v0[2], a1 = v1[2];
                float l0 = (a0 > 0.f) ? a0 : 0.01f*a0;
                float l1 = (a1 > 0.f) ? a1 : 0.01f*a1;
                *(float2*)(srow + 6 + 2*qd) =
                    make_float2(fmaxf(l0 + 1.1f, 1e-6f), fmaxf(l1 + 1.1f, 1e-6f));
            }
            // mu cols 20..29
            float* mrow = ob + 5120 + r*10;
            if (qd >= 2) {
                float a0 = v0[2], a1 = v1[2];
                float l0 = (a0 > 0.f) ? a0 : 0.01f*a0;
                float l1 = (a1 > 0.f) ? a1 : 0.01f*a1;
                *(float2*)(mrow + 2*qd - 4) = make_float2(l0 + 1.f, l1 + 1.f);
            }
            if (qd <= 2) {
                float a0 = v0[3], a1 = v1[3];
                float l0 = (a0 > 0.f) ? a0 : 0.01f*a0;
                float l1 = (a1 > 0.f) ? a1 : 0.01f*a1;
                *(float2*)(mrow + 4 + 2*qd) = make_float2(l0 + 1.f, l1 + 1.f);
            }
        }
    }
    __syncthreads();

    // ---- coalesced float4 store of pi/sigma/mu (640 float4 each) ----
    const float4* obv = (const float4*)ob;
    #pragma unroll
    for (int it = 0; it < 8; it++) {
        int idx = it*256 + tid;
        if (idx < 1920) {
            int reg = idx / 640, wi = idx % 640;
            long long goff = (reg == 0 ? PI_OFF : reg == 1 ? SG_OFF : MU_OFF) + m0*10;
            *((float4*)(out + goff) + wi) = obv[idx];
        }
    }
}

extern "C" void kernel_launch(void* const* d_in, const int* in_sizes, int n_in,
                              void* d_out, int out_size) {
    const float* pos_l    = (const float*)d_in[0];
    const float* pos_p    = (const float*)d_in[1];
    const float* Interact = (const float*)d_in[2];
    const int*   mask     = (const int*)d_in[3];
    const float* W_pi     = (const float*)d_in[4];
    const float* b_pi     = (const float*)d_in[5];
    const float* W_sigma  = (const float*)d_in[6];
    const float* b_sigma  = (const float*)d_in[7];
    const float* W_mu     = (const float*)d_in[8];
    const float* b_mu     = (const float*)d_in[9];
    float* out = (float*)d_out;

    cudaFuncSetAttribute(fused_kernel, cudaFuncAttributeMaxDynamicSharedMemorySize,
                         SMEM_BYTES);
    fused_kernel<<<BB * NL * 2, 256, SMEM_BYTES>>>(pos_l, pos_p, Interact, mask,
                                                   W_pi, b_pi, W_sigma, b_sigma,
                                                   W_mu, b_mu, out);
}